// round 6
// baseline (speedup 1.0000x reference)
#include <cuda_runtime.h>
#include <cuda_fp16.h>
#include <mma.h>

using namespace nvcuda;

#define D_FEAT  128
#define HIDDEN  256
#define NOUT    512      // 2*HIDDEN (A and B halves)
#define MAX_NODES 100000
#define MAX_NODES_PAD 100352   // 98 * 1024
#define MAX_EDGES 1601536

// Precomputed per-node tables (fp16): A' = W1a*h + b1, B = W1b*h
__device__ __half g_A[(size_t)MAX_NODES * HIDDEN];   // 51.2 MB
__device__ __half g_B[(size_t)MAX_NODES * HIDDEN];   // 51.2 MB
__device__ __half g_W[D_FEAT * NOUT];                // Wcat[k][j], 128 KB

// Counting-sort scratch
__device__ int g_cnt[MAX_NODES_PAD];
__device__ int g_blockSums[256];
__device__ int g_cursor[MAX_NODES];
__device__ int g_srcS[MAX_EDGES];
__device__ int g_dstS[MAX_EDGES];
__device__ int g_eidS[MAX_EDGES];

// ---------------------------------------------------------------------------
// Prep: Wcat[k][j] = W1_w[j][k] (j<256) | W1_w[j-256][128+k] (j>=256)
// ---------------------------------------------------------------------------
__global__ void prep_w_kernel(const float* __restrict__ W1) {
    int idx = blockIdx.x * blockDim.x + threadIdx.x;
    if (idx >= D_FEAT * NOUT) return;
    int k = idx / NOUT;
    int j = idx % NOUT;
    float v = (j < HIDDEN) ? W1[(size_t)j * (2 * D_FEAT) + k]
                           : W1[(size_t)(j - HIDDEN) * (2 * D_FEAT) + D_FEAT + k];
    g_W[(size_t)k * NOUT + j] = __float2half(v);
}

// ---------------------------------------------------------------------------
// Counting sort of edges by src
// ---------------------------------------------------------------------------
__global__ void zero_cnt_kernel(int n_pad) {
    int i = blockIdx.x * blockDim.x + threadIdx.x;
    if (i < n_pad) g_cnt[i] = 0;
}

__global__ void hist_kernel(const int* __restrict__ src, int E) {
    int e = blockIdx.x * blockDim.x + threadIdx.x;
    if (e < E) atomicAdd(&g_cnt[src[e]], 1);
}

// Per-block (1024 nodes) sums
__global__ void scan1_kernel() {
    int b = blockIdx.x, t = threadIdx.x;
    int idx = b * 1024 + t * 4;
    int s = g_cnt[idx] + g_cnt[idx + 1] + g_cnt[idx + 2] + g_cnt[idx + 3];
#pragma unroll
    for (int off = 16; off > 0; off >>= 1)
        s += __shfl_xor_sync(0xFFFFFFFFu, s, off);
    __shared__ int ws[8];
    if ((t & 31) == 0) ws[t >> 5] = s;
    __syncthreads();
    if (t == 0) {
        int tot = 0;
#pragma unroll
        for (int i = 0; i < 8; i++) tot += ws[i];
        g_blockSums[b] = tot;
    }
}

__global__ void scan2_kernel(int nb) {
    if (threadIdx.x == 0 && blockIdx.x == 0) {
        int run = 0;
        for (int i = 0; i < nb; i++) {
            int t = g_blockSums[i];
            g_blockSums[i] = run;
            run += t;
        }
    }
}

// Exclusive scan within each 1024-node block + blockSums base -> cursor
__global__ void scan3_kernel(int n_nodes) {
    int b = blockIdx.x, t = threadIdx.x;
    int lane = t & 31, warp = t >> 5;
    int idx = b * 1024 + t * 4;
    int v0 = g_cnt[idx], v1 = g_cnt[idx + 1], v2 = g_cnt[idx + 2], v3 = g_cnt[idx + 3];
    int s = v0 + v1 + v2 + v3;
    // warp inclusive scan
    int incl = s;
#pragma unroll
    for (int off = 1; off < 32; off <<= 1) {
        int n = __shfl_up_sync(0xFFFFFFFFu, incl, off);
        if (lane >= off) incl += n;
    }
    int excl = incl - s;
    __shared__ int ws[8];
    if (lane == 31) ws[warp] = incl;
    __syncthreads();
    int wbase = 0;
#pragma unroll
    for (int i = 0; i < 8; i++) wbase += (i < warp) ? ws[i] : 0;
    int prefix = g_blockSums[b] + wbase + excl;
    if (idx     < n_nodes) g_cursor[idx]     = prefix;
    if (idx + 1 < n_nodes) g_cursor[idx + 1] = prefix + v0;
    if (idx + 2 < n_nodes) g_cursor[idx + 2] = prefix + v0 + v1;
    if (idx + 3 < n_nodes) g_cursor[idx + 3] = prefix + v0 + v1 + v2;
}

__global__ void scatter_kernel(const int* __restrict__ src,
                               const int* __restrict__ dst, int E) {
    int e = blockIdx.x * blockDim.x + threadIdx.x;
    if (e >= E) return;
    int s = src[e];
    int pos = atomicAdd(&g_cursor[s], 1);
    g_srcS[pos] = s;
    g_dstS[pos] = dst[e];
    g_eidS[pos] = e;
}

// ---------------------------------------------------------------------------
// Precompute GEMM: C[n,512] = h[n,128] @ Wcat[128,512], fp32 accumulate.
// Block = 128 rows x 2 N-slices (grid.y = 2). W slice staged in smem.
// Dynamic smem 68 KB: sA (34816 B) + sW (34816 B, reused as fp32 staging).
// ---------------------------------------------------------------------------
#define MT 128
#define SLD 136

__global__ void __launch_bounds__(256) gemm_ab_kernel(
    const float* __restrict__ h, const float* __restrict__ b1, int n_nodes)
{
    extern __shared__ char dsm[];
    __half* sA = reinterpret_cast<__half*>(dsm);
    __half* sW = reinterpret_cast<__half*>(dsm + MT * SLD * 2);

    int mBase = blockIdx.x * MT;
    int wid = threadIdx.x >> 5;

    // Load h tile (fp32 -> fp16)
    for (int i = threadIdx.x; i < MT * (D_FEAT / 4); i += 256) {
        int r  = i >> 5;
        int c4 = i & 31;
        float4 v = make_float4(0.f, 0.f, 0.f, 0.f);
        int row = mBase + r;
        if (row < n_nodes) v = *(const float4*)(h + (size_t)row * D_FEAT + c4 * 4);
        __half2 lo = __floats2half2_rn(v.x, v.y);
        __half2 hi = __floats2half2_rn(v.z, v.w);
        uint2 pk;
        pk.x = *(const unsigned*)&lo;
        pk.y = *(const unsigned*)&hi;
        *(uint2*)(&sA[r * SLD + c4 * 4]) = pk;
    }

    for (int k2 = 0; k2 < 2; k2++) {
        int nBase = (blockIdx.y * 2 + k2) * MT;
        __syncthreads();

        for (int i = threadIdx.x; i < MT * (MT / 8); i += 256) {
            int k  = i >> 4;
            int c8 = i & 15;
            *(uint4*)(&sW[k * SLD + c8 * 8]) =
                *(const uint4*)(g_W + (size_t)k * NOUT + nBase + c8 * 8);
        }
        __syncthreads();

        wmma::fragment<wmma::accumulator, 16, 16, 16, float> acc[8];
#pragma unroll
        for (int f = 0; f < 8; f++) wmma::fill_fragment(acc[f], 0.0f);

#pragma unroll
        for (int k = 0; k < D_FEAT; k += 16) {
            wmma::fragment<wmma::matrix_a, 16, 16, 16, __half, wmma::row_major> fa;
            wmma::load_matrix_sync(fa, &sA[(wid * 16) * SLD + k], SLD);
#pragma unroll
            for (int f = 0; f < 8; f++) {
                wmma::fragment<wmma::matrix_b, 16, 16, 16, __half, wmma::row_major> fb;
                wmma::load_matrix_sync(fb, &sW[k * SLD + f * 16], SLD);
                wmma::mma_sync(acc[f], fa, fb, acc[f]);
            }
        }

        bool isA = (nBase < HIDDEN);
        __half* gOut = isA ? g_A : g_B;
        int jBase = isA ? nBase : (nBase - HIDDEN);

        float* sC = reinterpret_cast<float*>(sW);
#pragma unroll
        for (int nh = 0; nh < 2; nh++) {
            __syncthreads();
#pragma unroll
            for (int f = 0; f < 4; f++)
                wmma::store_matrix_sync(sC + wid * (16 * 64) + f * 16,
                                        acc[nh * 4 + f], 64, wmma::mem_row_major);
            __syncthreads();

            for (int i = threadIdx.x; i < MT * 8; i += 256) {
                int r = i >> 3;
                int g = i & 7;
                int row = mBase + r;
                if (row >= n_nodes) continue;
                int j = jBase + nh * 64 + g * 8;
                const float* p = sC + (r >> 4) * (16 * 64) + (r & 15) * 64 + g * 8;
                float v0 = p[0], v1 = p[1], v2 = p[2], v3 = p[3];
                float v4 = p[4], v5 = p[5], v6 = p[6], v7 = p[7];
                if (isA) {
                    float4 ba = *(const float4*)(b1 + j);
                    float4 bb = *(const float4*)(b1 + j + 4);
                    v0 += ba.x; v1 += ba.y; v2 += ba.z; v3 += ba.w;
                    v4 += bb.x; v5 += bb.y; v6 += bb.z; v7 += bb.w;
                }
                __half2 h0 = __floats2half2_rn(v0, v1);
                __half2 h1 = __floats2half2_rn(v2, v3);
                __half2 h2 = __floats2half2_rn(v4, v5);
                __half2 h3 = __floats2half2_rn(v6, v7);
                uint4 pk;
                pk.x = *(const unsigned*)&h0; pk.y = *(const unsigned*)&h1;
                pk.z = *(const unsigned*)&h2; pk.w = *(const unsigned*)&h3;
                *(uint4*)(gOut + (size_t)row * HIDDEN + j) = pk;
            }
        }
    }
}

// ---------------------------------------------------------------------------
// Edge kernel over src-sorted edges: 2 edges/warp, 16 lanes/edge.
// A rows: consecutive edges share src -> L1-allocating loads (hot).
// B rows: random -> .cg (L2 only). Result scattered to out[eid].
// ---------------------------------------------------------------------------
__device__ __forceinline__ uint4 ldg_cg_128(const void* p) {
    uint4 v;
    asm("ld.global.cg.v4.u32 {%0,%1,%2,%3}, [%4];"
        : "=r"(v.x), "=r"(v.y), "=r"(v.z), "=r"(v.w) : "l"(p));
    return v;
}

__global__ void __launch_bounds__(256) edge_kernel_sorted(
    const float* __restrict__ W2, const float* __restrict__ b2,
    float* __restrict__ out, int E)
{
    __shared__ float sW[HIDDEN];
    __shared__ float sb2;
    for (int i = threadIdx.x; i < HIDDEN; i += 256) sW[i] = W2[i];
    if (threadIdx.x == 0) sb2 = b2[0];
    __syncthreads();

    int lane = threadIdx.x & 31;
    int sub  = lane & 15;
    int e = blockIdx.x * 16 + (threadIdx.x >> 5) * 2 + (lane >> 4);

    float w[16];
#pragma unroll
    for (int i = 0; i < 16; i++) w[i] = sW[sub * 16 + i];

    float acc = 0.f;
    int eid = 0;
    if (e < E) {
        int s = g_srcS[e];
        int d = g_dstS[e];
        eid   = g_eidS[e];
        const __half* pA = g_A + (size_t)s * HIDDEN + sub * 16;
        const __half* pB = g_B + (size_t)d * HIDDEN + sub * 16;

        uint4 va0 = *(const uint4*)(pA);          // .ca — reused across edges
        uint4 va1 = *(const uint4*)(pA + 8);
        uint4 vb0 = ldg_cg_128(pB);               // random — skip L1
        uint4 vb1 = ldg_cg_128(pB + 8);

        const __half2* pa0 = (const __half2*)&va0;
        const __half2* pa1 = (const __half2*)&va1;
        const __half2* pb0 = (const __half2*)&vb0;
        const __half2* pb1 = (const __half2*)&vb1;
        const __half2 zero2 = __float2half2_rn(0.f);

#pragma unroll
        for (int i = 0; i < 4; i++) {
            __half2 z2 = __hmax2(__hadd2(pa0[i], pb0[i]), zero2);
            float2 f = __half22float2(z2);
            acc = fmaf(f.x, w[2 * i + 0], acc);
            acc = fmaf(f.y, w[2 * i + 1], acc);
        }
#pragma unroll
        for (int i = 0; i < 4; i++) {
            __half2 z2 = __hmax2(__hadd2(pa1[i], pb1[i]), zero2);
            float2 f = __half22float2(z2);
            acc = fmaf(f.x, w[8 + 2 * i + 0], acc);
            acc = fmaf(f.y, w[8 + 2 * i + 1], acc);
        }
    }

#pragma unroll
    for (int off = 8; off > 0; off >>= 1)
        acc += __shfl_xor_sync(0xFFFFFFFFu, acc, off);

    if (sub == 0 && e < E) out[eid] = acc + sb2;
}

// ---------------------------------------------------------------------------
extern "C" void kernel_launch(void* const* d_in, const int* in_sizes, int n_in,
                              void* d_out, int out_size)
{
    const float* h    = (const float*)d_in[0];
    const int*   src  = (const int*)d_in[1];
    const int*   dst  = (const int*)d_in[2];
    const float* W1_w = (const float*)d_in[3];
    const float* W1_b = (const float*)d_in[4];
    const float* W2_w = (const float*)d_in[5];
    const float* W2_b = (const float*)d_in[6];
    float* out = (float*)d_out;

    int n_nodes = in_sizes[0] / D_FEAT;
    int E = in_sizes[1];
    if (E > MAX_EDGES) E = MAX_EDGES;

    int nb = (n_nodes + 1023) / 1024;
    int n_pad = nb * 1024;

    // 1) Weight reorder
    prep_w_kernel<<<(D_FEAT * NOUT + 255) / 256, 256>>>(W1_w);

    // 2) Counting sort of edges by src (overlaps GEMM-independent work)
    zero_cnt_kernel<<<(n_pad + 255) / 256, 256>>>(n_pad);
    hist_kernel<<<(E + 255) / 256, 256>>>(src, E);
    scan1_kernel<<<nb, 256>>>();
    scan2_kernel<<<1, 32>>>(nb);
    scan3_kernel<<<nb, 256>>>(n_nodes);
    scatter_kernel<<<(E + 255) / 256, 256>>>(src, dst, E);

    // 3) Precompute A' (with b1) and B per node — 68 KB dynamic smem
    static int smem_set = 0;
    int smem_bytes = 2 * MT * SLD * 2;
    if (!smem_set) {
        cudaFuncSetAttribute(gemm_ab_kernel,
                             cudaFuncAttributeMaxDynamicSharedMemorySize,
                             smem_bytes);
        smem_set = 1;
    }
    dim3 ggrid((n_nodes + MT - 1) / MT, 2);
    gemm_ab_kernel<<<ggrid, 256, smem_bytes>>>(h, W1_b, n_nodes);

    // 4) Per-edge: gather (sorted), add, relu, dot, scatter out
    edge_kernel_sorted<<<(E + 15) / 16, 256>>>(W2_w, W2_b, out, E);
}

// round 7
// speedup vs baseline: 1.1185x; 1.1185x over previous
#include <cuda_runtime.h>
#include <cuda_fp16.h>
#include <mma.h>

using namespace nvcuda;

#define D_FEAT  128
#define HIDDEN  256
#define NOUT    512      // 2*HIDDEN (A and B halves)
#define MAX_NODES 100000
#define MAX_NODES_PAD 100352   // 98 * 1024
#define MAX_EDGES 1601536

// Precomputed per-node tables (fp16): A' = W1a*h + b1, B = W1b*h
__device__ __half g_A[(size_t)MAX_NODES * HIDDEN];   // 51.2 MB
__device__ __half g_B[(size_t)MAX_NODES * HIDDEN];   // 51.2 MB
__device__ __half g_W[D_FEAT * NOUT];                // Wcat[k][j], 128 KB

// CSR build scratch (counting sort by src)
__device__ int g_cnt[MAX_NODES_PAD];     // per-node degree (kept)
__device__ int g_blockSums[256];
__device__ int g_rowStart[MAX_NODES];    // CSR row starts (kept)
__device__ int g_cursor[MAX_NODES];      // scatter cursors (mutated)
__device__ int g_dstS[MAX_EDGES];
__device__ int g_eidS[MAX_EDGES];

// ---------------------------------------------------------------------------
// Prep: Wcat[k][j] = W1_w[j][k] (j<256) | W1_w[j-256][128+k] (j>=256)
// ---------------------------------------------------------------------------
__global__ void prep_w_kernel(const float* __restrict__ W1) {
    int idx = blockIdx.x * blockDim.x + threadIdx.x;
    if (idx >= D_FEAT * NOUT) return;
    int k = idx / NOUT;
    int j = idx % NOUT;
    float v = (j < HIDDEN) ? W1[(size_t)j * (2 * D_FEAT) + k]
                           : W1[(size_t)(j - HIDDEN) * (2 * D_FEAT) + D_FEAT + k];
    g_W[(size_t)k * NOUT + j] = __float2half(v);
}

// ---------------------------------------------------------------------------
// CSR build: histogram + scan + scatter (counting sort by src)
// ---------------------------------------------------------------------------
__global__ void zero_cnt_kernel(int n_pad) {
    int i = blockIdx.x * blockDim.x + threadIdx.x;
    if (i < n_pad) g_cnt[i] = 0;
}

__global__ void hist_kernel(const int* __restrict__ src, int E) {
    int e = blockIdx.x * blockDim.x + threadIdx.x;
    if (e < E) atomicAdd(&g_cnt[src[e]], 1);
}

__global__ void scan1_kernel() {
    int b = blockIdx.x, t = threadIdx.x;
    int idx = b * 1024 + t * 4;
    int s = g_cnt[idx] + g_cnt[idx + 1] + g_cnt[idx + 2] + g_cnt[idx + 3];
#pragma unroll
    for (int off = 16; off > 0; off >>= 1)
        s += __shfl_xor_sync(0xFFFFFFFFu, s, off);
    __shared__ int ws[8];
    if ((t & 31) == 0) ws[t >> 5] = s;
    __syncthreads();
    if (t == 0) {
        int tot = 0;
#pragma unroll
        for (int i = 0; i < 8; i++) tot += ws[i];
        g_blockSums[b] = tot;
    }
}

__global__ void scan2_kernel(int nb) {
    if (threadIdx.x == 0 && blockIdx.x == 0) {
        int run = 0;
        for (int i = 0; i < nb; i++) {
            int t = g_blockSums[i];
            g_blockSums[i] = run;
            run += t;
        }
    }
}

__global__ void scan3_kernel(int n_nodes) {
    int b = blockIdx.x, t = threadIdx.x;
    int lane = t & 31, warp = t >> 5;
    int idx = b * 1024 + t * 4;
    int v0 = g_cnt[idx], v1 = g_cnt[idx + 1], v2 = g_cnt[idx + 2], v3 = g_cnt[idx + 3];
    int s = v0 + v1 + v2 + v3;
    int incl = s;
#pragma unroll
    for (int off = 1; off < 32; off <<= 1) {
        int n = __shfl_up_sync(0xFFFFFFFFu, incl, off);
        if (lane >= off) incl += n;
    }
    int excl = incl - s;
    __shared__ int ws[8];
    if (lane == 31) ws[warp] = incl;
    __syncthreads();
    int wbase = 0;
#pragma unroll
    for (int i = 0; i < 8; i++) wbase += (i < warp) ? ws[i] : 0;
    int p0 = g_blockSums[b] + wbase + excl;
    int p1 = p0 + v0, p2 = p1 + v1, p3 = p2 + v2;
    if (idx     < n_nodes) { g_rowStart[idx]     = p0; g_cursor[idx]     = p0; }
    if (idx + 1 < n_nodes) { g_rowStart[idx + 1] = p1; g_cursor[idx + 1] = p1; }
    if (idx + 2 < n_nodes) { g_rowStart[idx + 2] = p2; g_cursor[idx + 2] = p2; }
    if (idx + 3 < n_nodes) { g_rowStart[idx + 3] = p3; g_cursor[idx + 3] = p3; }
}

__global__ void scatter_kernel(const int* __restrict__ src,
                               const int* __restrict__ dst, int E) {
    int e = blockIdx.x * blockDim.x + threadIdx.x;
    if (e >= E) return;
    int s = src[e];
    int pos = atomicAdd(&g_cursor[s], 1);
    g_dstS[pos] = dst[e];
    g_eidS[pos] = e;
}

// ---------------------------------------------------------------------------
// Precompute GEMM: C[n,512] = h[n,128] @ Wcat[128,512], fp32 accumulate.
// Block = 128 rows x 2 N-slices (grid.y = 2). W slice staged in smem.
// ---------------------------------------------------------------------------
#define MT 128
#define SLD 136

__global__ void __launch_bounds__(256) gemm_ab_kernel(
    const float* __restrict__ h, const float* __restrict__ b1, int n_nodes)
{
    extern __shared__ char dsm[];
    __half* sA = reinterpret_cast<__half*>(dsm);
    __half* sW = reinterpret_cast<__half*>(dsm + MT * SLD * 2);

    int mBase = blockIdx.x * MT;
    int wid = threadIdx.x >> 5;

    for (int i = threadIdx.x; i < MT * (D_FEAT / 4); i += 256) {
        int r  = i >> 5;
        int c4 = i & 31;
        float4 v = make_float4(0.f, 0.f, 0.f, 0.f);
        int row = mBase + r;
        if (row < n_nodes) v = *(const float4*)(h + (size_t)row * D_FEAT + c4 * 4);
        __half2 lo = __floats2half2_rn(v.x, v.y);
        __half2 hi = __floats2half2_rn(v.z, v.w);
        uint2 pk;
        pk.x = *(const unsigned*)&lo;
        pk.y = *(const unsigned*)&hi;
        *(uint2*)(&sA[r * SLD + c4 * 4]) = pk;
    }

    for (int k2 = 0; k2 < 2; k2++) {
        int nBase = (blockIdx.y * 2 + k2) * MT;
        __syncthreads();

        for (int i = threadIdx.x; i < MT * (MT / 8); i += 256) {
            int k  = i >> 4;
            int c8 = i & 15;
            *(uint4*)(&sW[k * SLD + c8 * 8]) =
                *(const uint4*)(g_W + (size_t)k * NOUT + nBase + c8 * 8);
        }
        __syncthreads();

        wmma::fragment<wmma::accumulator, 16, 16, 16, float> acc[8];
#pragma unroll
        for (int f = 0; f < 8; f++) wmma::fill_fragment(acc[f], 0.0f);

#pragma unroll
        for (int k = 0; k < D_FEAT; k += 16) {
            wmma::fragment<wmma::matrix_a, 16, 16, 16, __half, wmma::row_major> fa;
            wmma::load_matrix_sync(fa, &sA[(wid * 16) * SLD + k], SLD);
#pragma unroll
            for (int f = 0; f < 8; f++) {
                wmma::fragment<wmma::matrix_b, 16, 16, 16, __half, wmma::row_major> fb;
                wmma::load_matrix_sync(fb, &sW[k * SLD + f * 16], SLD);
                wmma::mma_sync(acc[f], fa, fb, acc[f]);
            }
        }

        bool isA = (nBase < HIDDEN);
        __half* gOut = isA ? g_A : g_B;
        int jBase = isA ? nBase : (nBase - HIDDEN);

        float* sC = reinterpret_cast<float*>(sW);
#pragma unroll
        for (int nh = 0; nh < 2; nh++) {
            __syncthreads();
#pragma unroll
            for (int f = 0; f < 4; f++)
                wmma::store_matrix_sync(sC + wid * (16 * 64) + f * 16,
                                        acc[nh * 4 + f], 64, wmma::mem_row_major);
            __syncthreads();

            for (int i = threadIdx.x; i < MT * 8; i += 256) {
                int r = i >> 3;
                int g = i & 7;
                int row = mBase + r;
                if (row >= n_nodes) continue;
                int j = jBase + nh * 64 + g * 8;
                const float* p = sC + (r >> 4) * (16 * 64) + (r & 15) * 64 + g * 8;
                float v0 = p[0], v1 = p[1], v2 = p[2], v3 = p[3];
                float v4 = p[4], v5 = p[5], v6 = p[6], v7 = p[7];
                if (isA) {
                    float4 ba = *(const float4*)(b1 + j);
                    float4 bb = *(const float4*)(b1 + j + 4);
                    v0 += ba.x; v1 += ba.y; v2 += ba.z; v3 += ba.w;
                    v4 += bb.x; v5 += bb.y; v6 += bb.z; v7 += bb.w;
                }
                __half2 h0 = __floats2half2_rn(v0, v1);
                __half2 h1 = __floats2half2_rn(v2, v3);
                __half2 h2 = __floats2half2_rn(v4, v5);
                __half2 h3 = __floats2half2_rn(v6, v7);
                uint4 pk;
                pk.x = *(const unsigned*)&h0; pk.y = *(const unsigned*)&h1;
                pk.z = *(const unsigned*)&h2; pk.w = *(const unsigned*)&h3;
                *(uint4*)(gOut + (size_t)row * HIDDEN + j) = pk;
            }
        }
    }
}

// ---------------------------------------------------------------------------
// CSR edge kernel: one warp per src node. A row held in registers; the
// warp's two 16-lane groups stream the node's edges (2 edges in flight),
// loading only B rows (.cg, L2-only). Scores scattered to out[eid].
// ---------------------------------------------------------------------------
__device__ __forceinline__ uint4 ldg_cg_128(const void* p) {
    uint4 v;
    asm("ld.global.cg.v4.u32 {%0,%1,%2,%3}, [%4];"
        : "=r"(v.x), "=r"(v.y), "=r"(v.z), "=r"(v.w) : "l"(p));
    return v;
}

__global__ void __launch_bounds__(256) edge_kernel_csr(
    const float* __restrict__ W2, const float* __restrict__ b2,
    float* __restrict__ out, int n_nodes)
{
    __shared__ float sW[HIDDEN];
    __shared__ float sb2;
    for (int i = threadIdx.x; i < HIDDEN; i += 256) sW[i] = W2[i];
    if (threadIdx.x == 0) sb2 = b2[0];
    __syncthreads();

    int warp = threadIdx.x >> 5;
    int lane = threadIdx.x & 31;
    int node = blockIdx.x * 8 + warp;
    if (node >= n_nodes) return;

    int sub = lane & 15;          // lane within 16-lane group
    int grp = lane >> 4;          // 0 or 1: which edge of the pair

    int start = g_rowStart[node];
    int deg   = g_cnt[node];
    if (deg == 0) return;

    // A row (with b1 folded) into registers: 16 halves per lane.
    const __half* pA = g_A + (size_t)node * HIDDEN + sub * 16;
    uint4 va0 = *(const uint4*)(pA);
    uint4 va1 = *(const uint4*)(pA + 8);
    const __half2* pa0 = (const __half2*)&va0;
    const __half2* pa1 = (const __half2*)&va1;

    float w[16];
#pragma unroll
    for (int i = 0; i < 16; i++) w[i] = sW[sub * 16 + i];

    const __half2 zero2 = __float2half2_rn(0.f);
    int iters = (deg + 1) >> 1;

    for (int it = 0; it < iters; it++) {
        int i = 2 * it + grp;
        bool valid = (i < deg);
        int e = start + (valid ? i : 0);
        int d   = g_dstS[e];
        int eid = g_eidS[e];

        const __half* pB = g_B + (size_t)d * HIDDEN + sub * 16;
        uint4 vb0 = ldg_cg_128(pB);
        uint4 vb1 = ldg_cg_128(pB + 8);
        const __half2* pb0 = (const __half2*)&vb0;
        const __half2* pb1 = (const __half2*)&vb1;

        float acc = 0.f;
#pragma unroll
        for (int q = 0; q < 4; q++) {
            __half2 z2 = __hmax2(__hadd2(pa0[q], pb0[q]), zero2);
            float2 f = __half22float2(z2);
            acc = fmaf(f.x, w[2 * q + 0], acc);
            acc = fmaf(f.y, w[2 * q + 1], acc);
        }
#pragma unroll
        for (int q = 0; q < 4; q++) {
            __half2 z2 = __hmax2(__hadd2(pa1[q], pb1[q]), zero2);
            float2 f = __half22float2(z2);
            acc = fmaf(f.x, w[8 + 2 * q + 0], acc);
            acc = fmaf(f.y, w[8 + 2 * q + 1], acc);
        }

        // reduce within each 16-lane group (offsets <= 8 stay in-group)
#pragma unroll
        for (int off = 8; off > 0; off >>= 1)
            acc += __shfl_xor_sync(0xFFFFFFFFu, acc, off);

        if (sub == 0 && valid) out[eid] = acc + sb2;
    }
}

// ---------------------------------------------------------------------------
extern "C" void kernel_launch(void* const* d_in, const int* in_sizes, int n_in,
                              void* d_out, int out_size)
{
    const float* h    = (const float*)d_in[0];
    const int*   src  = (const int*)d_in[1];
    const int*   dst  = (const int*)d_in[2];
    const float* W1_w = (const float*)d_in[3];
    const float* W1_b = (const float*)d_in[4];
    const float* W2_w = (const float*)d_in[5];
    const float* W2_b = (const float*)d_in[6];
    float* out = (float*)d_out;

    int n_nodes = in_sizes[0] / D_FEAT;
    int E = in_sizes[1];
    if (E > MAX_EDGES) E = MAX_EDGES;

    int nb = (n_nodes + 1023) / 1024;
    int n_pad = nb * 1024;

    // 1) Weight reorder
    prep_w_kernel<<<(D_FEAT * NOUT + 255) / 256, 256>>>(W1_w);

    // 2) CSR build (counting sort by src)
    zero_cnt_kernel<<<(n_pad + 255) / 256, 256>>>(n_pad);
    hist_kernel<<<(E + 255) / 256, 256>>>(src, E);
    scan1_kernel<<<nb, 256>>>();
    scan2_kernel<<<1, 32>>>(nb);
    scan3_kernel<<<nb, 256>>>(n_nodes);
    scatter_kernel<<<(E + 255) / 256, 256>>>(src, dst, E);

    // 3) Precompute A' (with b1) and B per node — 68 KB dynamic smem
    static int smem_set = 0;
    int smem_bytes = 2 * MT * SLD * 2;
    if (!smem_set) {
        cudaFuncSetAttribute(gemm_ab_kernel,
                             cudaFuncAttributeMaxDynamicSharedMemorySize,
                             smem_bytes);
        smem_set = 1;
    }
    dim3 ggrid((n_nodes + MT - 1) / MT, 2);
    gemm_ab_kernel<<<ggrid, 256, smem_bytes>>>(h, W1_b, n_nodes);

    // 4) Per-node warp: stream edges, gather B only, scatter scores
    edge_kernel_csr<<<(n_nodes + 7) / 8, 256>>>(W2_w, W2_b, out, n_nodes);
}

// round 8
// speedup vs baseline: 1.8852x; 1.6855x over previous
#include <cuda_runtime.h>
#include <cuda_fp16.h>
#include <mma.h>

using namespace nvcuda;

#define D_FEAT  128
#define HIDDEN  256
#define NOUT    512      // 2*HIDDEN (A and B halves)
#define MAX_NODES 100000

// Precomputed per-node tables (fp16): A' = W1a*h + b1, B = W1b*h
__device__ __half g_A[(size_t)MAX_NODES * HIDDEN];   // 51.2 MB
__device__ __half g_B[(size_t)MAX_NODES * HIDDEN];   // 51.2 MB
__device__ __half g_W[D_FEAT * NOUT];                // Wcat[k][j], 128 KB

// ---------------------------------------------------------------------------
// Prep: Wcat[k][j] = W1_w[j][k] (j<256) | W1_w[j-256][128+k] (j>=256)
// ---------------------------------------------------------------------------
__global__ void prep_w_kernel(const float* __restrict__ W1) {
    int idx = blockIdx.x * blockDim.x + threadIdx.x;
    if (idx >= D_FEAT * NOUT) return;
    int k = idx / NOUT;
    int j = idx % NOUT;
    float v = (j < HIDDEN) ? W1[(size_t)j * (2 * D_FEAT) + k]
                           : W1[(size_t)(j - HIDDEN) * (2 * D_FEAT) + D_FEAT + k];
    g_W[(size_t)k * NOUT + j] = __float2half(v);
}

// ---------------------------------------------------------------------------
// Precompute GEMM: C[n,512] = h[n,128] @ Wcat[128,512], fp32 accumulate.
// Block = 128 rows x 2 N-slices (grid.y = 2). W slice staged in smem.
// Dynamic smem 68 KB: sA (34816 B) + sW (34816 B, reused as fp32 staging).
// ---------------------------------------------------------------------------
#define MT 128
#define SLD 136

__global__ void __launch_bounds__(256) gemm_ab_kernel(
    const float* __restrict__ h, const float* __restrict__ b1, int n_nodes)
{
    extern __shared__ char dsm[];
    __half* sA = reinterpret_cast<__half*>(dsm);
    __half* sW = reinterpret_cast<__half*>(dsm + MT * SLD * 2);

    int mBase = blockIdx.x * MT;
    int wid = threadIdx.x >> 5;

    // Load h tile (fp32 -> fp16)
    for (int i = threadIdx.x; i < MT * (D_FEAT / 4); i += 256) {
        int r  = i >> 5;
        int c4 = i & 31;
        float4 v = make_float4(0.f, 0.f, 0.f, 0.f);
        int row = mBase + r;
        if (row < n_nodes) v = *(const float4*)(h + (size_t)row * D_FEAT + c4 * 4);
        __half2 lo = __floats2half2_rn(v.x, v.y);
        __half2 hi = __floats2half2_rn(v.z, v.w);
        uint2 pk;
        pk.x = *(const unsigned*)&lo;
        pk.y = *(const unsigned*)&hi;
        *(uint2*)(&sA[r * SLD + c4 * 4]) = pk;
    }

    for (int k2 = 0; k2 < 2; k2++) {
        int nBase = (blockIdx.y * 2 + k2) * MT;
        __syncthreads();

        for (int i = threadIdx.x; i < MT * (MT / 8); i += 256) {
            int k  = i >> 4;
            int c8 = i & 15;
            *(uint4*)(&sW[k * SLD + c8 * 8]) =
                *(const uint4*)(g_W + (size_t)k * NOUT + nBase + c8 * 8);
        }
        __syncthreads();

        wmma::fragment<wmma::accumulator, 16, 16, 16, float> acc[8];
#pragma unroll
        for (int f = 0; f < 8; f++) wmma::fill_fragment(acc[f], 0.0f);

#pragma unroll
        for (int k = 0; k < D_FEAT; k += 16) {
            wmma::fragment<wmma::matrix_a, 16, 16, 16, __half, wmma::row_major> fa;
            wmma::load_matrix_sync(fa, &sA[(wid * 16) * SLD + k], SLD);
#pragma unroll
            for (int f = 0; f < 8; f++) {
                wmma::fragment<wmma::matrix_b, 16, 16, 16, __half, wmma::row_major> fb;
                wmma::load_matrix_sync(fb, &sW[k * SLD + f * 16], SLD);
                wmma::mma_sync(acc[f], fa, fb, acc[f]);
            }
        }

        bool isA = (nBase < HIDDEN);
        __half* gOut = isA ? g_A : g_B;
        int jBase = isA ? nBase : (nBase - HIDDEN);

        float* sC = reinterpret_cast<float*>(sW);
#pragma unroll
        for (int nh = 0; nh < 2; nh++) {
            __syncthreads();
#pragma unroll
            for (int f = 0; f < 4; f++)
                wmma::store_matrix_sync(sC + wid * (16 * 64) + f * 16,
                                        acc[nh * 4 + f], 64, wmma::mem_row_major);
            __syncthreads();

            for (int i = threadIdx.x; i < MT * 8; i += 256) {
                int r = i >> 3;
                int g = i & 7;
                int row = mBase + r;
                if (row >= n_nodes) continue;
                int j = jBase + nh * 64 + g * 8;
                const float* p = sC + (r >> 4) * (16 * 64) + (r & 15) * 64 + g * 8;
                float v0 = p[0], v1 = p[1], v2 = p[2], v3 = p[3];
                float v4 = p[4], v5 = p[5], v6 = p[6], v7 = p[7];
                if (isA) {
                    float4 ba = *(const float4*)(b1 + j);
                    float4 bb = *(const float4*)(b1 + j + 4);
                    v0 += ba.x; v1 += ba.y; v2 += ba.z; v3 += ba.w;
                    v4 += bb.x; v5 += bb.y; v6 += bb.z; v7 += bb.w;
                }
                __half2 h0 = __floats2half2_rn(v0, v1);
                __half2 h1 = __floats2half2_rn(v2, v3);
                __half2 h2 = __floats2half2_rn(v4, v5);
                __half2 h3 = __floats2half2_rn(v6, v7);
                uint4 pk;
                pk.x = *(const unsigned*)&h0; pk.y = *(const unsigned*)&h1;
                pk.z = *(const unsigned*)&h2; pk.w = *(const unsigned*)&h3;
                *(uint4*)(gOut + (size_t)row * HIDDEN + j) = pk;
            }
        }
    }
}

// ---------------------------------------------------------------------------
// Edge kernel: 1 edge per warp, 4 edges batched per warp.
// Lane owns 8 CONTIGUOUS halves (16B) -> each LDG.128 covers the full 512B
// row with 100% byte utilization (4 lines, minimal L1tex wavefronts).
// All 8 gathers issued before compute (MLP=8). .cg = L2-only.
// ---------------------------------------------------------------------------
__device__ __forceinline__ uint4 ldg_cg_128(const void* p) {
    uint4 v;
    asm("ld.global.cg.v4.u32 {%0,%1,%2,%3}, [%4];"
        : "=r"(v.x), "=r"(v.y), "=r"(v.z), "=r"(v.w) : "l"(p));
    return v;
}

#define KE 4   // edges per warp

__global__ void __launch_bounds__(256) edge_kernel(
    const int* __restrict__ src, const int* __restrict__ dst,
    const float* __restrict__ W2, const float* __restrict__ b2,
    float* __restrict__ out, int E)
{
    __shared__ float sW[HIDDEN];
    __shared__ float sb2;
    for (int i = threadIdx.x; i < HIDDEN; i += 256) sW[i] = W2[i];
    if (threadIdx.x == 0) sb2 = b2[0];
    __syncthreads();

    int lane = threadIdx.x & 31;
    int warp = threadIdx.x >> 5;
    int eb = (blockIdx.x * 8 + warp) * KE;
    if (eb >= E) return;

    float w[8];
#pragma unroll
    for (int i = 0; i < 8; i++) w[i] = sW[lane * 8 + i];

    // Gather indices (clamped; stores masked below)
    int s[KE], d[KE];
#pragma unroll
    for (int i = 0; i < KE; i++) {
        int e = eb + i;
        int ec = (e < E) ? e : (E - 1);
        s[i] = __ldg(src + ec);
        d[i] = __ldg(dst + ec);
    }

    // Issue all table gathers up front (MLP = 2*KE)
    uint4 va[KE], vb[KE];
#pragma unroll
    for (int i = 0; i < KE; i++) {
        va[i] = ldg_cg_128(g_A + (size_t)s[i] * HIDDEN + lane * 8);
        vb[i] = ldg_cg_128(g_B + (size_t)d[i] * HIDDEN + lane * 8);
    }

    const __half2 zero2 = __float2half2_rn(0.f);

#pragma unroll
    for (int i = 0; i < KE; i++) {
        const __half2* pa = (const __half2*)&va[i];
        const __half2* pb = (const __half2*)&vb[i];
        float acc = 0.f;
#pragma unroll
        for (int q = 0; q < 4; q++) {
            __half2 z2 = __hmax2(__hadd2(pa[q], pb[q]), zero2);
            float2 f = __half22float2(z2);
            acc = fmaf(f.x, w[2 * q + 0], acc);
            acc = fmaf(f.y, w[2 * q + 1], acc);
        }
        // full-warp reduce (lane 0 gets the sum of all 256 dims)
#pragma unroll
        for (int off = 16; off > 0; off >>= 1)
            acc += __shfl_xor_sync(0xFFFFFFFFu, acc, off);
        if (lane == 0 && (eb + i) < E) out[eb + i] = acc + sb2;
    }
}

// ---------------------------------------------------------------------------
extern "C" void kernel_launch(void* const* d_in, const int* in_sizes, int n_in,
                              void* d_out, int out_size)
{
    const float* h    = (const float*)d_in[0];
    const int*   src  = (const int*)d_in[1];
    const int*   dst  = (const int*)d_in[2];
    const float* W1_w = (const float*)d_in[3];
    const float* W1_b = (const float*)d_in[4];
    const float* W2_w = (const float*)d_in[5];
    const float* W2_b = (const float*)d_in[6];
    float* out = (float*)d_out;

    int n_nodes = in_sizes[0] / D_FEAT;
    int E = in_sizes[1];

    // 1) Weight reorder
    prep_w_kernel<<<(D_FEAT * NOUT + 255) / 256, 256>>>(W1_w);

    // 2) Precompute A' (with b1) and B per node — 68 KB dynamic smem
    static int smem_set = 0;
    int smem_bytes = 2 * MT * SLD * 2;
    if (!smem_set) {
        cudaFuncSetAttribute(gemm_ab_kernel,
                             cudaFuncAttributeMaxDynamicSharedMemorySize,
                             smem_bytes);
        smem_set = 1;
    }
    dim3 ggrid((n_nodes + MT - 1) / MT, 2);
    gemm_ab_kernel<<<ggrid, 256, smem_bytes>>>(h, W1_b, n_nodes);

    // 3) Per-edge: gather, add, relu, dot (32 edges per block)
    int edges_per_block = 8 * KE;
    edge_kernel<<<(E + edges_per_block - 1) / edges_per_block, 256>>>(
        src, dst, W2_w, W2_b, out, E);
}

// round 9
// speedup vs baseline: 1.9603x; 1.0398x over previous
#include <cuda_runtime.h>
#include <cuda_fp16.h>
#include <mma.h>

using namespace nvcuda;

#define D_FEAT  128
#define HIDDEN  256
#define NOUT    512      // 2*HIDDEN (A and B halves)
#define MAX_NODES 100000

// Precomputed per-node tables (fp16): A' = W1a*h + b1, B = W1b*h
__device__ __half g_A[(size_t)MAX_NODES * HIDDEN];   // 51.2 MB
__device__ __half g_B[(size_t)MAX_NODES * HIDDEN];   // 51.2 MB
__device__ __half g_W[D_FEAT * NOUT];                // Wcat[k][j], 128 KB

// ---------------------------------------------------------------------------
// Prep: Wcat[k][j] = W1_w[j][k] (j<256) | W1_w[j-256][128+k] (j>=256)
// ---------------------------------------------------------------------------
__global__ void prep_w_kernel(const float* __restrict__ W1) {
    int idx = blockIdx.x * blockDim.x + threadIdx.x;
    if (idx >= D_FEAT * NOUT) return;
    int k = idx / NOUT;
    int j = idx % NOUT;
    float v = (j < HIDDEN) ? W1[(size_t)j * (2 * D_FEAT) + k]
                           : W1[(size_t)(j - HIDDEN) * (2 * D_FEAT) + D_FEAT + k];
    g_W[(size_t)k * NOUT + j] = __float2half(v);
}

// ---------------------------------------------------------------------------
// Precompute GEMM: C[n,512] = h[n,128] @ Wcat[128,512], fp32 accumulate.
// Block = 128 rows; 2 slices of 128 cols (grid.y = 2 -> A-pair / B-pair).
// Warp tile 32x64 (fb reuse x2, fa reuse x4). W slice 2 prefetched via
// cp.async during slice-1 compute. smem: sA + sW0 + sW1 = 104448 B.
// ---------------------------------------------------------------------------
#define MT 128
#define SLD 136          // padded leading dim (halves); 272B rows (odd 16B units)
#define TILE_B (MT * SLD * 2)   // 34816

__global__ void __launch_bounds__(256, 2) gemm_ab_kernel(
    const float* __restrict__ h, const float* __restrict__ b1, int n_nodes)
{
    extern __shared__ char dsm[];
    __half* sA  = reinterpret_cast<__half*>(dsm);
    __half* sW0 = reinterpret_cast<__half*>(dsm + TILE_B);
    __half* sW1 = reinterpret_cast<__half*>(dsm + 2 * TILE_B);

    int mBase = blockIdx.x * MT;
    int wid  = threadIdx.x >> 5;
    int wm   = (wid & 3) * 32;     // warp row offset within tile
    int wn   = (wid >> 2) * 64;    // warp col offset within slice

    int nSlice0 = blockIdx.y * 256;         // cols [nSlice0, nSlice0+128)
    int nSlice1 = nSlice0 + 128;

    // --- load h tile (fp32 -> fp16) ---
    for (int i = threadIdx.x; i < MT * (D_FEAT / 4); i += 256) {
        int r  = i >> 5;
        int c4 = i & 31;
        float4 v = make_float4(0.f, 0.f, 0.f, 0.f);
        int row = mBase + r;
        if (row < n_nodes) v = *(const float4*)(h + (size_t)row * D_FEAT + c4 * 4);
        __half2 lo = __floats2half2_rn(v.x, v.y);
        __half2 hi = __floats2half2_rn(v.z, v.w);
        uint2 pk;
        pk.x = *(const unsigned*)&lo;
        pk.y = *(const unsigned*)&hi;
        *(uint2*)(&sA[r * SLD + c4 * 4]) = pk;
    }

    // --- load W slice 0 (LDG+STS) ---
    for (int i = threadIdx.x; i < MT * 16; i += 256) {
        int k  = i >> 4;
        int c8 = i & 15;
        *(uint4*)(&sW0[k * SLD + c8 * 8]) =
            *(const uint4*)(g_W + (size_t)k * NOUT + nSlice0 + c8 * 8);
    }

    // --- prefetch W slice 1 via cp.async ---
    for (int i = threadIdx.x; i < MT * 16; i += 256) {
        int k  = i >> 4;
        int c8 = i & 15;
        unsigned saddr = (unsigned)__cvta_generic_to_shared(&sW1[k * SLD + c8 * 8]);
        const void* gp = g_W + (size_t)k * NOUT + nSlice1 + c8 * 8;
        asm volatile("cp.async.ca.shared.global [%0], [%1], 16;\n"
                     :: "r"(saddr), "l"(gp));
    }
    asm volatile("cp.async.commit_group;\n");

    __syncthreads();   // sA + sW0 ready

    float* sC = reinterpret_cast<float*>(sW0);   // epilogue staging (ld=68)

#pragma unroll
    for (int k2 = 0; k2 < 2; k2++) {
        const __half* sW = (k2 == 0) ? sW0 : sW1;
        int nSlice = (k2 == 0) ? nSlice0 : nSlice1;

        wmma::fragment<wmma::accumulator, 16, 16, 16, float> acc[2][4];
#pragma unroll
        for (int i = 0; i < 2; i++)
#pragma unroll
            for (int j = 0; j < 4; j++) wmma::fill_fragment(acc[i][j], 0.0f);

#pragma unroll
        for (int k = 0; k < D_FEAT; k += 16) {
            wmma::fragment<wmma::matrix_a, 16, 16, 16, __half, wmma::row_major> fa[2];
            wmma::load_matrix_sync(fa[0], &sA[(wm     ) * SLD + k], SLD);
            wmma::load_matrix_sync(fa[1], &sA[(wm + 16) * SLD + k], SLD);
#pragma unroll
            for (int j = 0; j < 4; j++) {
                wmma::fragment<wmma::matrix_b, 16, 16, 16, __half, wmma::row_major> fb;
                wmma::load_matrix_sync(fb, &sW[k * SLD + wn + j * 16], SLD);
                wmma::mma_sync(acc[0][j], fa[0], fb, acc[0][j]);
                wmma::mma_sync(acc[1][j], fa[1], fb, acc[1][j]);
            }
        }

        bool isA = (nSlice < HIDDEN);
        __half* gOut = isA ? g_A : g_B;
        int jBase = isA ? nSlice : (nSlice - HIDDEN);

        // Epilogue: two column-half passes through sC (128 x 64, ld=68 fp32).
#pragma unroll
        for (int p = 0; p < 2; p++) {
            __syncthreads();     // sC region free (slice compute / prior pass done)
            if ((wid >> 2) == p) {
#pragma unroll
                for (int i = 0; i < 2; i++)
#pragma unroll
                    for (int j = 0; j < 4; j++)
                        wmma::store_matrix_sync(
                            sC + (size_t)(wm + i * 16) * 68 + j * 16,
                            acc[i][j], 68, wmma::mem_row_major);
            }
            __syncthreads();

            for (int i = threadIdx.x; i < MT * 8; i += 256) {
                int r = i >> 3;
                int g = i & 7;
                int row = mBase + r;
                if (row >= n_nodes) continue;
                int j = jBase + p * 64 + g * 8;
                const float* q = sC + (size_t)r * 68 + g * 8;
                float v0 = q[0], v1 = q[1], v2 = q[2], v3 = q[3];
                float v4 = q[4], v5 = q[5], v6 = q[6], v7 = q[7];
                if (isA) {
                    float4 ba = *(const float4*)(b1 + j);
                    float4 bb = *(const float4*)(b1 + j + 4);
                    v0 += ba.x; v1 += ba.y; v2 += ba.z; v3 += ba.w;
                    v4 += bb.x; v5 += bb.y; v6 += bb.z; v7 += bb.w;
                }
                __half2 h0 = __floats2half2_rn(v0, v1);
                __half2 h1 = __floats2half2_rn(v2, v3);
                __half2 h2 = __floats2half2_rn(v4, v5);
                __half2 h3 = __floats2half2_rn(v6, v7);
                uint4 pk;
                pk.x = *(const unsigned*)&h0; pk.y = *(const unsigned*)&h1;
                pk.z = *(const unsigned*)&h2; pk.w = *(const unsigned*)&h3;
                *(uint4*)(gOut + (size_t)row * HIDDEN + j) = pk;
            }
        }

        if (k2 == 0) {
            asm volatile("cp.async.wait_group 0;\n");
            __syncthreads();   // sW1 visible to all
        }
    }
}

// ---------------------------------------------------------------------------
// Edge kernel: 1 edge per warp, 4 edges batched per warp.
// Lane owns 8 CONTIGUOUS halves (16B) -> 100% byte utilization per LDG.128.
// All 8 gathers issued before compute (MLP=8). .cg = L2-only.
// ---------------------------------------------------------------------------
__device__ __forceinline__ uint4 ldg_cg_128(const void* p) {
    uint4 v;
    asm("ld.global.cg.v4.u32 {%0,%1,%2,%3}, [%4];"
        : "=r"(v.x), "=r"(v.y), "=r"(v.z), "=r"(v.w) : "l"(p));
    return v;
}

#define KE 4   // edges per warp

__global__ void __launch_bounds__(256) edge_kernel(
    const int* __restrict__ src, const int* __restrict__ dst,
    const float* __restrict__ W2, const float* __restrict__ b2,
    float* __restrict__ out, int E)
{
    __shared__ float sW[HIDDEN];
    __shared__ float sb2;
    for (int i = threadIdx.x; i < HIDDEN; i += 256) sW[i] = W2[i];
    if (threadIdx.x == 0) sb2 = b2[0];
    __syncthreads();

    int lane = threadIdx.x & 31;
    int warp = threadIdx.x >> 5;
    int eb = (blockIdx.x * 8 + warp) * KE;
    if (eb >= E) return;

    float w[8];
#pragma unroll
    for (int i = 0; i < 8; i++) w[i] = sW[lane * 8 + i];

    int s[KE], d[KE];
#pragma unroll
    for (int i = 0; i < KE; i++) {
        int e = eb + i;
        int ec = (e < E) ? e : (E - 1);
        s[i] = __ldg(src + ec);
        d[i] = __ldg(dst + ec);
    }

    uint4 va[KE], vb[KE];
#pragma unroll
    for (int i = 0; i < KE; i++) {
        va[i] = ldg_cg_128(g_A + (size_t)s[i] * HIDDEN + lane * 8);
        vb[i] = ldg_cg_128(g_B + (size_t)d[i] * HIDDEN + lane * 8);
    }

    const __half2 zero2 = __float2half2_rn(0.f);

#pragma unroll
    for (int i = 0; i < KE; i++) {
        const __half2* pa = (const __half2*)&va[i];
        const __half2* pb = (const __half2*)&vb[i];
        float acc = 0.f;
#pragma unroll
        for (int q = 0; q < 4; q++) {
            __half2 z2 = __hmax2(__hadd2(pa[q], pb[q]), zero2);
            float2 f = __half22float2(z2);
            acc = fmaf(f.x, w[2 * q + 0], acc);
            acc = fmaf(f.y, w[2 * q + 1], acc);
        }
#pragma unroll
        for (int off = 16; off > 0; off >>= 1)
            acc += __shfl_xor_sync(0xFFFFFFFFu, acc, off);
        if (lane == 0 && (eb + i) < E) out[eb + i] = acc + sb2;
    }
}

// ---------------------------------------------------------------------------
extern "C" void kernel_launch(void* const* d_in, const int* in_sizes, int n_in,
                              void* d_out, int out_size)
{
    const float* h    = (const float*)d_in[0];
    const int*   src  = (const int*)d_in[1];
    const int*   dst  = (const int*)d_in[2];
    const float* W1_w = (const float*)d_in[3];
    const float* W1_b = (const float*)d_in[4];
    const float* W2_w = (const float*)d_in[5];
    const float* W2_b = (const float*)d_in[6];
    float* out = (float*)d_out;

    int n_nodes = in_sizes[0] / D_FEAT;
    int E = in_sizes[1];

    // 1) Weight reorder
    prep_w_kernel<<<(D_FEAT * NOUT + 255) / 256, 256>>>(W1_w);

    // 2) Precompute A' (with b1) and B per node — 102 KB dynamic smem
    static int smem_set = 0;
    int smem_bytes = 3 * TILE_B;   // 104448
    if (!smem_set) {
        cudaFuncSetAttribute(gemm_ab_kernel,
                             cudaFuncAttributeMaxDynamicSharedMemorySize,
                             smem_bytes);
        smem_set = 1;
    }
    dim3 ggrid((n_nodes + MT - 1) / MT, 2);
    gemm_ab_kernel<<<ggrid, 256, smem_bytes>>>(h, W1_b, n_nodes);

    // 3) Per-edge: gather, add, relu, dot (32 edges per block)
    int edges_per_block = 8 * KE;
    edge_kernel<<<(E + edges_per_block - 1) / edges_per_block, 256>>>(
        src, dst, W2_w, W2_b, out, E);
}